// round 8
// baseline (speedup 1.0000x reference)
#include <cuda_runtime.h>
#include <cuda_fp16.h>
#include <math.h>
#include <stdint.h>

#define CCH 512
#define NPX 4096
typedef __half fp16;

static const size_t NH  = (size_t)NPX * CCH;
static const size_t NN  = (size_t)NPX * NPX;
static const size_t NQK = (size_t)NPX * 1024;
#define WS ((size_t)CCH * CCH)

// ---------------- static scratch ----------------
__device__ fp16 g_ht[(size_t)2 * NPX * CCH];    // GN output [B][N][C]
__device__ fp16 g_w[(size_t)4 * CCH * CCH];     // wq,wk,wv,wp fp16
__device__ fp16 g_qk[(size_t)2 * NPX * 1024];   // Q cols 0-511, K cols 512-1023
__device__ fp16 g_v[(size_t)2 * CCH * NPX];     // [B][C][N]
__device__ fp16 g_o[(size_t)2 * NPX * CCH];     // [B][N][C]
__device__ fp16 g_s16[(size_t)2 * NPX * NPX];   // scores fp16
__device__ fp16 g_a[(size_t)2 * NPX * NPX];     // attn fp16

// ---------------- helpers ----------------
__device__ __forceinline__ uint32_t smem_u32(const void* p) {
    uint32_t a;
    asm("{ .reg .u64 t; cvta.to.shared.u64 t, %1; cvt.u32.u64 %0, t; }" : "=r"(a) : "l"(p));
    return a;
}
__device__ __forceinline__ uint32_t pack2(fp16 a, fp16 b) {
    __half2 t; t.x = a; t.y = b;
    return *reinterpret_cast<uint32_t*>(&t);
}
__device__ __forceinline__ void cp16(uint32_t s, const void* g) {
    asm volatile("cp.async.cg.shared.global [%0], [%1], 16;" :: "r"(s), "l"(g));
}
__device__ __forceinline__ void ldsm4(uint32_t* r, uint32_t addr) {
    asm volatile("ldmatrix.sync.aligned.m8n8.x4.shared.b16 {%0,%1,%2,%3}, [%4];"
        : "=r"(r[0]), "=r"(r[1]), "=r"(r[2]), "=r"(r[3]) : "r"(addr));
}
__device__ __forceinline__ void mma16816(float* d, const uint32_t* a, uint32_t b0, uint32_t b1) {
    asm volatile("mma.sync.aligned.m16n8k16.row.col.f32.f16.f16.f32 "
        "{%0,%1,%2,%3}, {%4,%5,%6,%7}, {%8,%9}, {%0,%1,%2,%3};"
        : "+f"(d[0]), "+f"(d[1]), "+f"(d[2]), "+f"(d[3])
        : "r"(a[0]), "r"(a[1]), "r"(a[2]), "r"(a[3]), "r"(b0), "r"(b1));
}
__device__ __forceinline__ void mma16816h(uint32_t* d, const uint32_t* a, uint32_t b0, uint32_t b1) {
    asm volatile("mma.sync.aligned.m16n8k16.row.col.f16.f16.f16.f16 "
        "{%0,%1}, {%2,%3,%4,%5}, {%6,%7}, {%0,%1};"
        : "+r"(d[0]), "+r"(d[1])
        : "r"(a[0]), "r"(a[1]), "r"(a[2]), "r"(a[3]), "r"(b0), "r"(b1));
}

// ---------------- weight convert ----------------
__global__ void __launch_bounds__(256) wconv_kernel(const float* __restrict__ w0,
                                                    const float* __restrict__ w1,
                                                    const float* __restrict__ w2,
                                                    const float* __restrict__ w3,
                                                    fp16* __restrict__ o) {
    size_t i = (size_t)blockIdx.x * 256 + threadIdx.x;
    size_t which = i / WS, r = i - which * WS;
    const float* w = (which == 0) ? w0 : (which == 1) ? w1 : (which == 2) ? w2 : w3;
    o[i] = __float2half(w[r]);
}

// ---------------- GroupNorm + transpose -> fp16 [B][N][C] ----------------
__global__ void __launch_bounds__(256) gn_kernel(const float* __restrict__ x,
                                                 const float* __restrict__ gamma,
                                                 const float* __restrict__ beta,
                                                 fp16* __restrict__ ht) {
    int b = blockIdx.x >> 5;
    int g = blockIdx.x & 31;
    const size_t base = ((size_t)b * CCH + (size_t)g * 16) * NPX;
    const float4* xp = (const float4*)(x + base);
    const int TOT4 = 16 * NPX / 4;
    int tid = threadIdx.x;

    float s = 0.f, ss = 0.f;
    for (int i = tid; i < TOT4; i += 256) {
        float4 v = xp[i];
        s  += v.x + v.y + v.z + v.w;
        ss += v.x * v.x + v.y * v.y + v.z * v.z + v.w * v.w;
    }
    __shared__ float rs[8], rss[8];
    #pragma unroll
    for (int o = 16; o > 0; o >>= 1) {
        s  += __shfl_xor_sync(0xffffffffu, s, o);
        ss += __shfl_xor_sync(0xffffffffu, ss, o);
    }
    if ((tid & 31) == 0) { rs[tid >> 5] = s; rss[tid >> 5] = ss; }
    __syncthreads();
    float S = 0.f, SS = 0.f;
    #pragma unroll
    for (int w = 0; w < 8; w++) { S += rs[w]; SS += rss[w]; }
    const float inv_cnt = 1.0f / (float)(16 * NPX);
    float mean = S * inv_cnt;
    float var  = SS * inv_cnt - mean * mean;
    float rstd = rsqrtf(var + 1e-6f);

    __shared__ float sga[16], sbe[16];
    if (tid < 16) {
        int c = g * 16 + tid;
        float ga = gamma[c] * rstd;
        sga[tid] = ga;
        sbe[tid] = beta[c] - mean * ga;
    }
    __shared__ float xs[16][256];
    __syncthreads();

    for (int p0 = 0; p0 < NPX; p0 += 256) {
        #pragma unroll
        for (int c = 0; c < 16; c++) xs[c][tid] = x[base + (size_t)c * NPX + p0 + tid];
        __syncthreads();
        uint32_t hw[8];
        #pragma unroll
        for (int c2 = 0; c2 < 8; c2++) {
            float v0 = xs[2 * c2][tid]     * sga[2 * c2]     + sbe[2 * c2];
            float v1 = xs[2 * c2 + 1][tid] * sga[2 * c2 + 1] + sbe[2 * c2 + 1];
            hw[c2] = pack2(__float2half(v0), __float2half(v1));
        }
        size_t o = ((size_t)b * NPX + p0 + tid) * CCH + g * 16;
        ((uint4*)(g_ht + o))[0] = make_uint4(hw[0], hw[1], hw[2], hw[3]);
        ((uint4*)(g_ht + o))[1] = make_uint4(hw[4], hw[5], hw[6], hw[7]);
        __syncthreads();
    }
    (void)ht;
}

// ---------------- softmax fp16 -> fp16 ----------------
__global__ void __launch_bounds__(256) softmax_kernel(const fp16* __restrict__ S,
                                                      fp16* __restrict__ a) {
    size_t row = blockIdx.x;
    const __half2* p = (const __half2*)(S + row * NPX);
    int tid = threadIdx.x;
    float2 r[8];
    float m = -1e30f;
    #pragma unroll
    for (int i = 0; i < 8; i++) {
        __half2 h2 = p[tid + i * 256];
        r[i] = __half22float2(h2);
        m = fmaxf(m, fmaxf(r[i].x, r[i].y));
    }
    __shared__ float red[8];
    #pragma unroll
    for (int o = 16; o > 0; o >>= 1) m = fmaxf(m, __shfl_xor_sync(0xffffffffu, m, o));
    if ((tid & 31) == 0) red[tid >> 5] = m;
    __syncthreads();
    float bm = red[0];
    #pragma unroll
    for (int w = 1; w < 8; w++) bm = fmaxf(bm, red[w]);
    __syncthreads();
    float s = 0.f;
    #pragma unroll
    for (int i = 0; i < 8; i++) {
        r[i].x = __expf(r[i].x - bm); r[i].y = __expf(r[i].y - bm);
        s += r[i].x + r[i].y;
    }
    #pragma unroll
    for (int o = 16; o > 0; o >>= 1) s += __shfl_xor_sync(0xffffffffu, s, o);
    if ((tid & 31) == 0) red[tid >> 5] = s;
    __syncthreads();
    float bs = 0.f;
    #pragma unroll
    for (int w = 0; w < 8; w++) bs += red[w];
    float inv = 1.0f / bs;
    #pragma unroll
    for (int i = 0; i < 8; i++) {
        size_t idx = row * NPX + (tid + i * 256) * 2;
        *(uint32_t*)(a + idx) = pack2(__float2half(r[i].x * inv), __float2half(r[i].y * inv));
    }
}

// ================= f32-acc GEMM (projections): CTA 128x256, warp 64x64 =================
#define ROWB  144
#define STG_A (128 * ROWB)
#define STG_B (256 * ROWB)
#define STG   (STG_A + STG_B)
__global__ void gemm_hmma(
    const fp16* __restrict__ A, int ldA, size_t strideA,
    const fp16* __restrict__ B, int ldB, size_t strideB,
    int K,
    float* __restrict__ outF32, fp16* __restrict__ outH,
    int ldD, size_t strideD,
    float scale,
    const float* __restrict__ biasRow,
    const float* __restrict__ biasCol, const float* __restrict__ biasCol2,
    const float* __restrict__ resid)
{
    extern __shared__ char smemraw[];
    int tid = threadIdx.x, wid = tid >> 5, lane = tid & 31;
    int m0 = blockIdx.y * 128, n0 = blockIdx.x * 256, bz = blockIdx.z;
    A += (size_t)bz * strideA;
    B += (size_t)bz * strideB;

    uint32_t base = smem_u32(smemraw);
    int wm = wid & 1, wn = wid >> 1;
    const int nch = K >> 6;

    float acc[4][8][4];
    #pragma unroll
    for (int a = 0; a < 4; a++)
        #pragma unroll
        for (int b = 0; b < 8; b++)
            #pragma unroll
            for (int c = 0; c < 4; c++) acc[a][b][c] = 0.f;

    auto load_chunk = [&](int i) {
        int st = i % 3;
        size_t kb = (size_t)i * 64;
        uint32_t sa = base + st * STG;
        uint32_t sb = sa + STG_A;
        #pragma unroll
        for (int r = 0; r < 4; r++) {
            int u = tid + r * 256;
            int row = u >> 3, cs = u & 7;
            cp16(sa + (uint32_t)(row * ROWB + cs * 16),
                 A + (size_t)(m0 + row) * ldA + kb + cs * 8);
        }
        #pragma unroll
        for (int r = 0; r < 8; r++) {
            int u = tid + r * 256;
            int row = u >> 3, cs = u & 7;
            cp16(sb + (uint32_t)(row * ROWB + cs * 16),
                 B + (size_t)(n0 + row) * ldB + kb + cs * 8);
        }
    };

    load_chunk(0);
    asm volatile("cp.async.commit_group;" ::: "memory");
    if (nch > 1) load_chunk(1);
    asm volatile("cp.async.commit_group;" ::: "memory");

    uint32_t a_off[4], b_off[4];
    #pragma unroll
    for (int mi = 0; mi < 4; mi++) {
        int row = wm * 64 + mi * 16 + (lane & 15);
        a_off[mi] = (uint32_t)(row * ROWB + ((lane >> 4) * 8) * 2);
    }
    #pragma unroll
    for (int nb = 0; nb < 4; nb++) {
        int row = wn * 64 + nb * 16 + ((lane >> 4) << 3) + (lane & 7);
        b_off[nb] = (uint32_t)(row * ROWB + ((((lane >> 3) & 1) << 3)) * 2);
    }

    for (int i = 0; i < nch; i++) {
        if (i < nch - 1) asm volatile("cp.async.wait_group 1;" ::: "memory");
        else             asm volatile("cp.async.wait_group 0;" ::: "memory");
        __syncthreads();
        if (i + 2 < nch) {
            load_chunk(i + 2);
            asm volatile("cp.async.commit_group;" ::: "memory");
        }

        uint32_t sa = base + (i % 3) * STG;
        uint32_t sb = sa + STG_A;

        uint32_t afr[2][4][4], bfr[2][4][4];
        #pragma unroll
        for (int mi = 0; mi < 4; mi++) ldsm4(afr[0][mi], sa + a_off[mi]);
        #pragma unroll
        for (int nb = 0; nb < 4; nb++) ldsm4(bfr[0][nb], sb + b_off[nb]);

        #pragma unroll
        for (int kk = 0; kk < 4; kk++) {
            int cur = kk & 1, nxt = cur ^ 1;
            if (kk < 3) {
                uint32_t ko = (uint32_t)((kk + 1) * 32);
                #pragma unroll
                for (int mi = 0; mi < 4; mi++) ldsm4(afr[nxt][mi], sa + a_off[mi] + ko);
                #pragma unroll
                for (int nb = 0; nb < 4; nb++) ldsm4(bfr[nxt][nb], sb + b_off[nb] + ko);
            }
            #pragma unroll
            for (int mi = 0; mi < 4; mi++)
                #pragma unroll
                for (int ni = 0; ni < 8; ni++)
                    mma16816(acc[mi][ni], afr[cur][mi],
                             bfr[cur][ni >> 1][(ni & 1) * 2], bfr[cur][ni >> 1][(ni & 1) * 2 + 1]);
        }
    }

    int r4 = lane >> 2;
    int c2 = lane & 3;
    float* of = outF32 ? outF32 + (size_t)bz * strideD : nullptr;
    fp16* oh  = outH   ? outH   + (size_t)bz * strideD : nullptr;
    const float* rp = resid ? resid + (size_t)bz * strideD : nullptr;

    #pragma unroll
    for (int mi = 0; mi < 4; mi++) {
        #pragma unroll
        for (int half = 0; half < 2; half++) {
            int m = m0 + wm * 64 + mi * 16 + half * 8 + r4;
            float brow = biasRow ? biasRow[m] : 0.f;
            #pragma unroll
            for (int ni = 0; ni < 8; ni++) {
                int n = n0 + wn * 64 + ni * 8 + c2 * 2;
                float v0 = acc[mi][ni][half * 2 + 0] * scale + brow;
                float v1 = acc[mi][ni][half * 2 + 1] * scale + brow;
                if (biasCol) {
                    const float* bc = (biasCol2 && n >= 512) ? biasCol2 - 512 : biasCol;
                    v0 += bc[n]; v1 += bc[n + 1];
                }
                size_t off = (size_t)m * ldD + n;
                if (rp) {
                    float2 q = *(const float2*)(rp + off);
                    v0 += q.x; v1 += q.y;
                }
                if (of) *(float2*)(of + off) = make_float2(v0, v1);
                if (oh) *(uint32_t*)(oh + off) = pack2(__float2half(v0), __float2half(v1));
            }
        }
    }
}

// ================= f16-acc GEMM (scores/AV): CTA 128x128, warp 64x32 =================
// f16 accumulate within each K=64 chunk, promote to fp32 master per chunk.
#define HSTG_A (128 * ROWB)
#define HSTG   (2 * HSTG_A)          // 36864 per stage
__global__ void gemm_hmma_f16acc(
    const fp16* __restrict__ A, int ldA, size_t strideA,
    const fp16* __restrict__ B, int ldB, size_t strideB,
    int K,
    fp16* __restrict__ outH,
    int ldD, size_t strideD,
    float scale)
{
    extern __shared__ char smemraw[];
    int tid = threadIdx.x, wid = tid >> 5, lane = tid & 31;
    int m0 = blockIdx.y * 128, n0 = blockIdx.x * 128, bz = blockIdx.z;
    A += (size_t)bz * strideA;
    B += (size_t)bz * strideB;

    uint32_t base = smem_u32(smemraw);
    int wm = wid & 1, wn = wid >> 1;     // 2 x 4 warps; warp tile 64(m) x 32(n)
    const int nch = K >> 6;

    float acc[4][4][4];
    #pragma unroll
    for (int a = 0; a < 4; a++)
        #pragma unroll
        for (int b = 0; b < 4; b++)
            #pragma unroll
            for (int c = 0; c < 4; c++) acc[a][b][c] = 0.f;

    auto load_chunk = [&](int i) {
        int st = i % 3;
        size_t kb = (size_t)i * 64;
        uint32_t sa = base + st * HSTG;
        uint32_t sb = sa + HSTG_A;
        #pragma unroll
        for (int r = 0; r < 4; r++) {
            int u = tid + r * 256;
            int row = u >> 3, cs = u & 7;
            cp16(sa + (uint32_t)(row * ROWB + cs * 16),
                 A + (size_t)(m0 + row) * ldA + kb + cs * 8);
            cp16(sb + (uint32_t)(row * ROWB + cs * 16),
                 B + (size_t)(n0 + row) * ldB + kb + cs * 8);
        }
    };

    load_chunk(0);
    asm volatile("cp.async.commit_group;" ::: "memory");
    if (nch > 1) load_chunk(1);
    asm volatile("cp.async.commit_group;" ::: "memory");

    uint32_t a_off[4], b_off[2];
    #pragma unroll
    for (int mi = 0; mi < 4; mi++) {
        int row = wm * 64 + mi * 16 + (lane & 15);
        a_off[mi] = (uint32_t)(row * ROWB + ((lane >> 4) * 8) * 2);
    }
    #pragma unroll
    for (int nb = 0; nb < 2; nb++) {
        int row = wn * 32 + nb * 16 + ((lane >> 4) << 3) + (lane & 7);
        b_off[nb] = (uint32_t)(row * ROWB + ((((lane >> 3) & 1) << 3)) * 2);
    }

    for (int i = 0; i < nch; i++) {
        if (i < nch - 1) asm volatile("cp.async.wait_group 1;" ::: "memory");
        else             asm volatile("cp.async.wait_group 0;" ::: "memory");
        __syncthreads();
        if (i + 2 < nch) {
            load_chunk(i + 2);
            asm volatile("cp.async.commit_group;" ::: "memory");
        }

        uint32_t sa = base + (i % 3) * HSTG;
        uint32_t sb = sa + HSTG_A;

        uint32_t hacc[4][4][2];
        #pragma unroll
        for (int mi = 0; mi < 4; mi++)
            #pragma unroll
            for (int ni = 0; ni < 4; ni++) { hacc[mi][ni][0] = 0u; hacc[mi][ni][1] = 0u; }

        uint32_t afr[2][4][4], bfr[2][2][4];
        #pragma unroll
        for (int mi = 0; mi < 4; mi++) ldsm4(afr[0][mi], sa + a_off[mi]);
        #pragma unroll
        for (int nb = 0; nb < 2; nb++) ldsm4(bfr[0][nb], sb + b_off[nb]);

        #pragma unroll
        for (int kk = 0; kk < 4; kk++) {
            int cur = kk & 1, nxt = cur ^ 1;
            if (kk < 3) {
                uint32_t ko = (uint32_t)((kk + 1) * 32);
                #pragma unroll
                for (int mi = 0; mi < 4; mi++) ldsm4(afr[nxt][mi], sa + a_off[mi] + ko);
                #pragma unroll
                for (int nb = 0; nb < 2; nb++) ldsm4(bfr[nxt][nb], sb + b_off[nb] + ko);
            }
            #pragma unroll
            for (int mi = 0; mi < 4; mi++)
                #pragma unroll
                for (int ni = 0; ni < 4; ni++)
                    mma16816h(hacc[mi][ni], afr[cur][mi],
                              bfr[cur][ni >> 1][(ni & 1) * 2], bfr[cur][ni >> 1][(ni & 1) * 2 + 1]);
        }

        // promote chunk f16 partials into fp32 master
        #pragma unroll
        for (int mi = 0; mi < 4; mi++)
            #pragma unroll
            for (int ni = 0; ni < 4; ni++) {
                float2 lo = __half22float2(*(const __half2*)&hacc[mi][ni][0]);
                float2 hi = __half22float2(*(const __half2*)&hacc[mi][ni][1]);
                acc[mi][ni][0] += lo.x; acc[mi][ni][1] += lo.y;
                acc[mi][ni][2] += hi.x; acc[mi][ni][3] += hi.y;
            }
    }

    // ---------------- epilogue ----------------
    int r4 = lane >> 2;
    int c2 = lane & 3;
    fp16* oh = outH + (size_t)bz * strideD;

    #pragma unroll
    for (int mi = 0; mi < 4; mi++) {
        #pragma unroll
        for (int half = 0; half < 2; half++) {
            int m = m0 + wm * 64 + mi * 16 + half * 8 + r4;
            #pragma unroll
            for (int ni = 0; ni < 4; ni++) {
                int n = n0 + wn * 32 + ni * 8 + c2 * 2;
                float v0 = acc[mi][ni][half * 2 + 0] * scale;
                float v1 = acc[mi][ni][half * 2 + 1] * scale;
                size_t off = (size_t)m * ldD + n;
                *(uint32_t*)(oh + off) = pack2(__float2half(v0), __float2half(v1));
            }
        }
    }
}

// ---------------- launch ----------------
extern "C" void kernel_launch(void* const* d_in, const int* in_sizes, int n_in,
                              void* d_out, int out_size) {
    const float* x     = (const float*)d_in[0];
    const float* gamma = (const float*)d_in[1];
    const float* beta  = (const float*)d_in[2];
    const float* wq    = (const float*)d_in[3];
    const float* bq    = (const float*)d_in[4];
    const float* wk    = (const float*)d_in[5];
    const float* bk    = (const float*)d_in[6];
    const float* wv    = (const float*)d_in[7];
    const float* bv    = (const float*)d_in[8];
    const float* wp    = (const float*)d_in[9];
    const float* bp    = (const float*)d_in[10];
    float* out = (float*)d_out;

    fp16 *ht, *w, *qk, *v, *o, *s16, *a;
    cudaGetSymbolAddress((void**)&ht, g_ht);
    cudaGetSymbolAddress((void**)&w, g_w);
    cudaGetSymbolAddress((void**)&qk, g_qk);
    cudaGetSymbolAddress((void**)&v, g_v);
    cudaGetSymbolAddress((void**)&o, g_o);
    cudaGetSymbolAddress((void**)&s16, g_s16);
    cudaGetSymbolAddress((void**)&a, g_a);

    const int SMEM_DYN  = 3 * STG;     // 162 KB (f32-acc kernel)
    const int SMEM_DYNH = 3 * HSTG;    // 108 KB (f16-acc kernel)
    cudaFuncSetAttribute(gemm_hmma, cudaFuncAttributeMaxDynamicSharedMemorySize, SMEM_DYN);
    cudaFuncSetAttribute(gemm_hmma_f16acc, cudaFuncAttributeMaxDynamicSharedMemorySize, SMEM_DYNH);

    wconv_kernel<<<4 * (int)(WS / 256), 256>>>(wq, wk, wv, wp, w);
    gn_kernel<<<64, 256>>>(x, gamma, beta, ht);

    // QK fused: D[4096,1024] = hT @ [wq;wk]^T -> fp16
    gemm_hmma<<<dim3(1024 / 256, NPX / 128, 2), 256, SMEM_DYN>>>(
        ht, CCH, NH, w, CCH, 0, CCH,
        nullptr, qk, 1024, NQK, 1.0f, nullptr, bq, bk, nullptr);

    // V: [512,4096] -> fp16, biasRow=bv
    gemm_hmma<<<dim3(NPX / 256, CCH / 128, 2), 256, SMEM_DYN>>>(
        w + 2 * WS, CCH, 0, ht, CCH, NH, CCH,
        nullptr, v, NPX, NH, 1.0f, bv, nullptr, nullptr, nullptr);

    // scores (f16-acc chunks): fp16 [4096,4096]
    const float scale = 1.0f / sqrtf((float)CCH);
    gemm_hmma_f16acc<<<dim3(NPX / 128, NPX / 128, 2), 256, SMEM_DYNH>>>(
        qk, 1024, NQK, qk + 512, 1024, NQK, CCH,
        s16, NPX, NN, scale);

    softmax_kernel<<<2 * NPX, 256>>>(s16, a);

    // O = attn @ V^T (f16-acc chunks): [4096,512] -> fp16
    gemm_hmma_f16acc<<<dim3(CCH / 128, NPX / 128, 2), 256, SMEM_DYNH>>>(
        a, NPX, NN, v, NPX, NH, NPX,
        o, CCH, NH, 1.0f);

    // out = x + Wp @ O^T + bp: fp32 [512,4096]
    gemm_hmma<<<dim3(NPX / 256, CCH / 128, 2), 256, SMEM_DYN>>>(
        w + 3 * WS, CCH, 0, o, CCH, NH, CCH,
        out, nullptr, NPX, (size_t)CCH * NPX, 1.0f, bp, nullptr, nullptr, x);
}

// round 9
// speedup vs baseline: 1.2805x; 1.2805x over previous
#include <cuda_runtime.h>
#include <cuda_fp16.h>
#include <math.h>
#include <stdint.h>

#define CCH 512
#define NPX 4096
typedef __half fp16;

static const size_t NH   = (size_t)NPX * CCH;
static const size_t NN   = (size_t)NPX * NPX;
static const size_t NQKV = (size_t)NPX * 1536;
#define WS ((size_t)CCH * CCH)

// ---------------- static scratch ----------------
__device__ fp16  g_ht[(size_t)2 * NPX * CCH];    // GN output [B][N][C]
__device__ fp16  g_w[(size_t)4 * CCH * CCH];     // wq,wk,wv,wp fp16
__device__ float g_bqkv[1536];                   // concat bq|bk|bv
__device__ fp16  g_qkv[(size_t)2 * NPX * 1536];  // [B][N][1536]: Q|K|VT
__device__ fp16  g_wv[(size_t)2 * CCH * NPX];    // WpV [B][C][N]
__device__ fp16  g_E[(size_t)2 * NPX * NPX];     // exp(scores) fp16
__device__ float g_part[(size_t)2 * NPX * 16];   // per-(row, nblock) exp partial sums
__device__ float g_invs[(size_t)2 * NPX];        // 1/rowsum

// ---------------- helpers ----------------
__device__ __forceinline__ uint32_t smem_u32(const void* p) {
    uint32_t a;
    asm("{ .reg .u64 t; cvta.to.shared.u64 t, %1; cvt.u32.u64 %0, t; }" : "=r"(a) : "l"(p));
    return a;
}
__device__ __forceinline__ uint32_t pack2(fp16 a, fp16 b) {
    __half2 t; t.x = a; t.y = b;
    return *reinterpret_cast<uint32_t*>(&t);
}
__device__ __forceinline__ void cp16(uint32_t s, const void* g) {
    asm volatile("cp.async.cg.shared.global [%0], [%1], 16;" :: "r"(s), "l"(g));
}
__device__ __forceinline__ void ldsm4(uint32_t* r, uint32_t addr) {
    asm volatile("ldmatrix.sync.aligned.m8n8.x4.shared.b16 {%0,%1,%2,%3}, [%4];"
        : "=r"(r[0]), "=r"(r[1]), "=r"(r[2]), "=r"(r[3]) : "r"(addr));
}
__device__ __forceinline__ void mma16816(float* d, const uint32_t* a, uint32_t b0, uint32_t b1) {
    asm volatile("mma.sync.aligned.m16n8k16.row.col.f32.f16.f16.f32 "
        "{%0,%1,%2,%3}, {%4,%5,%6,%7}, {%8,%9}, {%0,%1,%2,%3};"
        : "+f"(d[0]), "+f"(d[1]), "+f"(d[2]), "+f"(d[3])
        : "r"(a[0]), "r"(a[1]), "r"(a[2]), "r"(a[3]), "r"(b0), "r"(b1));
}

// ---------------- weight convert ----------------
__global__ void __launch_bounds__(256) wconv_kernel(const float* __restrict__ w0,
                                                    const float* __restrict__ w1,
                                                    const float* __restrict__ w2,
                                                    const float* __restrict__ w3,
                                                    fp16* __restrict__ o) {
    size_t i = (size_t)blockIdx.x * 256 + threadIdx.x;
    size_t which = i / WS, r = i - which * WS;
    const float* w = (which == 0) ? w0 : (which == 1) ? w1 : (which == 2) ? w2 : w3;
    o[i] = __float2half(w[r]);
}

// ---------------- bias concat ----------------
__global__ void prep_kernel(const float* __restrict__ bq, const float* __restrict__ bk,
                            const float* __restrict__ bv) {
    int i = blockIdx.x * 512 + threadIdx.x;
    g_bqkv[i] = (i < 512) ? bq[i] : ((i < 1024) ? bk[i - 512] : bv[i - 1024]);
}

// ---------------- GroupNorm + transpose -> fp16 [B][N][C] ----------------
__global__ void __launch_bounds__(256) gn_kernel(const float* __restrict__ x,
                                                 const float* __restrict__ gamma,
                                                 const float* __restrict__ beta) {
    int b = blockIdx.x >> 5;
    int g = blockIdx.x & 31;
    const size_t base = ((size_t)b * CCH + (size_t)g * 16) * NPX;
    const float4* xp = (const float4*)(x + base);
    const int TOT4 = 16 * NPX / 4;
    int tid = threadIdx.x;

    float s = 0.f, ss = 0.f;
    for (int i = tid; i < TOT4; i += 256) {
        float4 v = xp[i];
        s  += v.x + v.y + v.z + v.w;
        ss += v.x * v.x + v.y * v.y + v.z * v.z + v.w * v.w;
    }
    __shared__ float rs[8], rss[8];
    #pragma unroll
    for (int o = 16; o > 0; o >>= 1) {
        s  += __shfl_xor_sync(0xffffffffu, s, o);
        ss += __shfl_xor_sync(0xffffffffu, ss, o);
    }
    if ((tid & 31) == 0) { rs[tid >> 5] = s; rss[tid >> 5] = ss; }
    __syncthreads();
    float S = 0.f, SS = 0.f;
    #pragma unroll
    for (int w = 0; w < 8; w++) { S += rs[w]; SS += rss[w]; }
    const float inv_cnt = 1.0f / (float)(16 * NPX);
    float mean = S * inv_cnt;
    float var  = SS * inv_cnt - mean * mean;
    float rstd = rsqrtf(var + 1e-6f);

    __shared__ float sga[16], sbe[16];
    if (tid < 16) {
        int c = g * 16 + tid;
        float ga = gamma[c] * rstd;
        sga[tid] = ga;
        sbe[tid] = beta[c] - mean * ga;
    }
    __shared__ float xs[16][256];
    __syncthreads();

    for (int p0 = 0; p0 < NPX; p0 += 256) {
        #pragma unroll
        for (int c = 0; c < 16; c++) xs[c][tid] = x[base + (size_t)c * NPX + p0 + tid];
        __syncthreads();
        uint32_t hw[8];
        #pragma unroll
        for (int c2 = 0; c2 < 8; c2++) {
            float v0 = xs[2 * c2][tid]     * sga[2 * c2]     + sbe[2 * c2];
            float v1 = xs[2 * c2 + 1][tid] * sga[2 * c2 + 1] + sbe[2 * c2 + 1];
            hw[c2] = pack2(__float2half(v0), __float2half(v1));
        }
        size_t o = ((size_t)b * NPX + p0 + tid) * CCH + g * 16;
        ((uint4*)(g_ht + o))[0] = make_uint4(hw[0], hw[1], hw[2], hw[3]);
        ((uint4*)(g_ht + o))[1] = make_uint4(hw[4], hw[5], hw[6], hw[7]);
        __syncthreads();
    }
}

// ---------------- rowsum reduce: inv = 1/sum(partials) ----------------
__global__ void rowsum_kernel() {
    int i = blockIdx.x * 256 + threadIdx.x;      // 0..8191
    const float* p = g_part + (size_t)i * 16;
    float s = 0.f;
    #pragma unroll
    for (int k = 0; k < 16; k++) s += p[k];
    g_invs[i] = 1.0f / s;
}

// ================= f32-acc GEMM: CTA 128x256, warp 64x64, BK=64, 3-stage =================
#define ROWB  144
#define STG_A (128 * ROWB)
#define STG_B (256 * ROWB)
#define STG   (STG_A + STG_B)

#define GEMM_MAINLOOP() \
    uint32_t base = smem_u32(smemraw); \
    int wm = wid & 1, wn = wid >> 1; \
    const int nch = K >> 6; \
    float acc[4][8][4]; \
    _Pragma("unroll") \
    for (int a_ = 0; a_ < 4; a_++) \
        _Pragma("unroll") \
        for (int b_ = 0; b_ < 8; b_++) \
            _Pragma("unroll") \
            for (int c_ = 0; c_ < 4; c_++) acc[a_][b_][c_] = 0.f; \
    auto load_chunk = [&](int i) { \
        int st = i % 3; \
        size_t kb = (size_t)i * 64; \
        uint32_t sa = base + st * STG; \
        uint32_t sb = sa + STG_A; \
        _Pragma("unroll") \
        for (int r = 0; r < 4; r++) { \
            int u = tid + r * 256; \
            int row = u >> 3, cs = u & 7; \
            cp16(sa + (uint32_t)(row * ROWB + cs * 16), \
                 A + (size_t)(m0 + row) * ldA + kb + cs * 8); \
        } \
        _Pragma("unroll") \
        for (int r = 0; r < 8; r++) { \
            int u = tid + r * 256; \
            int row = u >> 3, cs = u & 7; \
            cp16(sb + (uint32_t)(row * ROWB + cs * 16), \
                 B + (size_t)(n0 + row) * ldB + kb + cs * 8); \
        } \
    }; \
    load_chunk(0); \
    asm volatile("cp.async.commit_group;" ::: "memory"); \
    if (nch > 1) load_chunk(1); \
    asm volatile("cp.async.commit_group;" ::: "memory"); \
    uint32_t a_off[4], b_off[4]; \
    _Pragma("unroll") \
    for (int mi = 0; mi < 4; mi++) { \
        int row = wm * 64 + mi * 16 + (lane & 15); \
        a_off[mi] = (uint32_t)(row * ROWB + ((lane >> 4) * 8) * 2); \
    } \
    _Pragma("unroll") \
    for (int nb = 0; nb < 4; nb++) { \
        int row = wn * 64 + nb * 16 + ((lane >> 4) << 3) + (lane & 7); \
        b_off[nb] = (uint32_t)(row * ROWB + ((((lane >> 3) & 1) << 3)) * 2); \
    } \
    for (int i = 0; i < nch; i++) { \
        if (i < nch - 1) asm volatile("cp.async.wait_group 1;" ::: "memory"); \
        else             asm volatile("cp.async.wait_group 0;" ::: "memory"); \
        __syncthreads(); \
        if (i + 2 < nch) { \
            load_chunk(i + 2); \
            asm volatile("cp.async.commit_group;" ::: "memory"); \
        } \
        uint32_t sa = base + (i % 3) * STG; \
        uint32_t sb = sa + STG_A; \
        uint32_t afr[2][4][4], bfr[2][4][4]; \
        _Pragma("unroll") \
        for (int mi = 0; mi < 4; mi++) ldsm4(afr[0][mi], sa + a_off[mi]); \
        _Pragma("unroll") \
        for (int nb = 0; nb < 4; nb++) ldsm4(bfr[0][nb], sb + b_off[nb]); \
        _Pragma("unroll") \
        for (int kk = 0; kk < 4; kk++) { \
            int cur = kk & 1, nxt = cur ^ 1; \
            if (kk < 3) { \
                uint32_t ko = (uint32_t)((kk + 1) * 32); \
                _Pragma("unroll") \
                for (int mi = 0; mi < 4; mi++) ldsm4(afr[nxt][mi], sa + a_off[mi] + ko); \
                _Pragma("unroll") \
                for (int nb = 0; nb < 4; nb++) ldsm4(bfr[nxt][nb], sb + b_off[nb] + ko); \
            } \
            _Pragma("unroll") \
            for (int mi = 0; mi < 4; mi++) \
                _Pragma("unroll") \
                for (int ni = 0; ni < 8; ni++) \
                    mma16816(acc[mi][ni], afr[cur][mi], \
                             bfr[cur][ni >> 1][(ni & 1) * 2], bfr[cur][ni >> 1][(ni & 1) * 2 + 1]); \
        } \
    }

// ---- general GEMM: optional fp32/fp16 out, biasRow/biasCol, perN scale, residual ----
__global__ void gemm_hmma(
    const fp16* __restrict__ A, int ldA, size_t strideA,
    const fp16* __restrict__ B, int ldB, size_t strideB,
    int K,
    float* __restrict__ outF32, fp16* __restrict__ outH,
    int ldD, size_t strideD,
    float scale,
    const float* __restrict__ biasRow,
    const float* __restrict__ biasCol,
    const float* __restrict__ perN,          // multiplies result by perN[bz*NPX + n]
    const float* __restrict__ resid)
{
    extern __shared__ char smemraw[];
    int tid = threadIdx.x, wid = tid >> 5, lane = tid & 31;
    int m0 = blockIdx.y * 128, n0 = blockIdx.x * 256, bz = blockIdx.z;
    A += (size_t)bz * strideA;
    B += (size_t)bz * strideB;

    GEMM_MAINLOOP()

    int r4 = lane >> 2;
    int c2 = lane & 3;
    float* of = outF32 ? outF32 + (size_t)bz * strideD : nullptr;
    fp16* oh  = outH   ? outH   + (size_t)bz * strideD : nullptr;
    const float* rp = resid ? resid + (size_t)bz * strideD : nullptr;
    const float* pn = perN ? perN + (size_t)bz * NPX : nullptr;

    #pragma unroll
    for (int mi = 0; mi < 4; mi++) {
        #pragma unroll
        for (int half = 0; half < 2; half++) {
            int m = m0 + wm * 64 + mi * 16 + half * 8 + r4;
            float brow = biasRow ? biasRow[m] : 0.f;
            #pragma unroll
            for (int ni = 0; ni < 8; ni++) {
                int n = n0 + wn * 64 + ni * 8 + c2 * 2;
                float v0 = acc[mi][ni][half * 2 + 0] * scale;
                float v1 = acc[mi][ni][half * 2 + 1] * scale;
                if (pn) { v0 *= pn[n]; v1 *= pn[n + 1]; }
                v0 += brow; v1 += brow;
                if (biasCol) { v0 += biasCol[n]; v1 += biasCol[n + 1]; }
                size_t off = (size_t)m * ldD + n;
                if (rp) {
                    float2 q = *(const float2*)(rp + off);
                    v0 += q.x; v1 += q.y;
                }
                if (of) *(float2*)(of + off) = make_float2(v0, v1);
                if (oh) *(uint32_t*)(oh + off) = pack2(__float2half(v0), __float2half(v1));
            }
        }
    }
}

// ---- scores GEMM: writes E=exp(scale*s) fp16 + deterministic per-row partial sums ----
__global__ void gemm_scores(
    const fp16* __restrict__ A, int ldA, size_t strideA,
    const fp16* __restrict__ B, int ldB, size_t strideB,
    int K,
    fp16* __restrict__ outE, int ldD, size_t strideD,
    float scale)
{
    extern __shared__ char smemraw[];
    int tid = threadIdx.x, wid = tid >> 5, lane = tid & 31;
    int m0 = blockIdx.y * 128, n0 = blockIdx.x * 256, bz = blockIdx.z;
    A += (size_t)bz * strideA;
    B += (size_t)bz * strideB;

    GEMM_MAINLOOP()

    int r4 = lane >> 2;
    int c2 = lane & 3;
    fp16* oh = outE + (size_t)bz * strideD;
    float rsum[8];
    #pragma unroll
    for (int r = 0; r < 8; r++) rsum[r] = 0.f;

    #pragma unroll
    for (int mi = 0; mi < 4; mi++) {
        #pragma unroll
        for (int half = 0; half < 2; half++) {
            int m = m0 + wm * 64 + mi * 16 + half * 8 + r4;
            float rs = 0.f;
            #pragma unroll
            for (int ni = 0; ni < 8; ni++) {
                int n = n0 + wn * 64 + ni * 8 + c2 * 2;
                float e0 = __expf(acc[mi][ni][half * 2 + 0] * scale);
                float e1 = __expf(acc[mi][ni][half * 2 + 1] * scale);
                *(uint32_t*)(oh + (size_t)m * ldD + n) = pack2(__float2half(e0), __float2half(e1));
                rs += e0 + e1;
            }
            rsum[mi * 2 + half] = rs;
        }
    }
    // reduce over c2 (lane bits 0-1): lanes with c2==0 hold per-(warp,row) sum over 64 cols
    #pragma unroll
    for (int r = 0; r < 8; r++) {
        rsum[r] += __shfl_xor_sync(0xffffffffu, rsum[r], 1);
        rsum[r] += __shfl_xor_sync(0xffffffffu, rsum[r], 2);
    }
    __syncthreads();                 // stage smem now free for reuse
    float* sp = (float*)smemraw;     // [128 rows][4 wn]
    if (c2 == 0) {
        #pragma unroll
        for (int mi = 0; mi < 4; mi++)
            #pragma unroll
            for (int half = 0; half < 2; half++) {
                int rl = wm * 64 + mi * 16 + half * 8 + r4;
                sp[rl * 4 + wn] = rsum[mi * 2 + half];
            }
    }
    __syncthreads();
    if (tid < 128) {
        float s = sp[tid * 4] + sp[tid * 4 + 1] + sp[tid * 4 + 2] + sp[tid * 4 + 3];
        g_part[((size_t)bz * NPX + m0 + tid) * 16 + blockIdx.x] = s;
    }
}

// ---------------- launch ----------------
extern "C" void kernel_launch(void* const* d_in, const int* in_sizes, int n_in,
                              void* d_out, int out_size) {
    const float* x     = (const float*)d_in[0];
    const float* gamma = (const float*)d_in[1];
    const float* beta  = (const float*)d_in[2];
    const float* wq    = (const float*)d_in[3];
    const float* bq    = (const float*)d_in[4];
    const float* wk    = (const float*)d_in[5];
    const float* bk    = (const float*)d_in[6];
    const float* wv    = (const float*)d_in[7];
    const float* bv    = (const float*)d_in[8];
    const float* wp    = (const float*)d_in[9];
    const float* bp    = (const float*)d_in[10];
    float* out = (float*)d_out;

    fp16 *ht, *w, *qkv, *wv16, *E;
    float *bqkv, *invs;
    cudaGetSymbolAddress((void**)&ht, g_ht);
    cudaGetSymbolAddress((void**)&w, g_w);
    cudaGetSymbolAddress((void**)&qkv, g_qkv);
    cudaGetSymbolAddress((void**)&wv16, g_wv);
    cudaGetSymbolAddress((void**)&E, g_E);
    cudaGetSymbolAddress((void**)&bqkv, g_bqkv);
    cudaGetSymbolAddress((void**)&invs, g_invs);

    const int SMEM_DYN = 3 * STG;    // 162 KB
    cudaFuncSetAttribute(gemm_hmma, cudaFuncAttributeMaxDynamicSharedMemorySize, SMEM_DYN);
    cudaFuncSetAttribute(gemm_scores, cudaFuncAttributeMaxDynamicSharedMemorySize, SMEM_DYN);

    wconv_kernel<<<4 * (int)(WS / 256), 256>>>(wq, wk, wv, wp, w);
    prep_kernel<<<3, 512>>>(bq, bk, bv);
    gn_kernel<<<64, 256>>>(x, gamma, beta);

    // QKV fused: D[4096,1536] = ht @ [wq;wk;wv]^T + bqkv -> fp16 (Q | K | VT)
    gemm_hmma<<<dim3(1536 / 256, NPX / 128, 2), 256, SMEM_DYN>>>(
        ht, CCH, NH, w, CCH, 0, CCH,
        nullptr, qkv, 1536, NQKV, 1.0f, nullptr, bqkv, nullptr, nullptr);

    // WpV: D[512,4096] = Wp @ VT^T -> fp16  (independent of scores)
    gemm_hmma<<<dim3(NPX / 256, CCH / 128, 2), 256, SMEM_DYN>>>(
        w + 3 * WS, CCH, 0, qkv + 1024, 1536, NQKV, CCH,
        nullptr, wv16, NPX, NH, 1.0f, nullptr, nullptr, nullptr, nullptr);

    // scores -> E = exp(scale * Q@K^T) fp16, + per-row partial sums
    const float scale = 1.0f / sqrtf((float)CCH);
    gemm_scores<<<dim3(NPX / 256, NPX / 128, 2), 256, SMEM_DYN>>>(
        qkv, 1536, NQKV, qkv + 512, 1536, NQKV, CCH,
        E, NPX, NN, scale);

    // inverse row sums
    rowsum_kernel<<<2 * NPX / 256, 256>>>();

    // final: out[c,i] = (sum_j WpV[c,j]*E[i,j]) * invs[i] + bp[c] + x[c,i]
    gemm_hmma<<<dim3(NPX / 256, CCH / 128, 2), 256, SMEM_DYN>>>(
        wv16, NPX, NH, E, NPX, NN, NPX,
        out, nullptr, NPX, (size_t)CCH * NPX, 1.0f, bp, nullptr, invs, x);
}